// round 10
// baseline (speedup 1.0000x reference)
#include <cuda_runtime.h>

#define NTHREADS 256
#define BLOCKS_PER_SM 4
#define NBLOCKS  (148 * BLOCKS_PER_SM)   // persistent grid

// Oct scheme: 8 lanes per point. Lane s = t&7:
//   h = s&1   : rank half (float4 slot within texel)
//   c = s>>1  : corner; r = c&1 (row), pcol = c>>1 (column)
// Each lane: 1 gather per plane (3 total), weight w = roww * colw,
// partial matvec for outputs {2c, 2c+1} over its half's 12 features.

struct PS { int base; float w; };

__device__ __forceinline__ PS plane_setup(float u, float v, int h, int r, int pcol)
{
    // x = ((u+1)*512 - 1)*0.5 == u*256 + 255.5 (<=1 ulp; bilinear continuous)
    float x = fmaf(u, 256.0f, 255.5f);
    float y = fmaf(v, 256.0f, 255.5f);
    x = fminf(fmaxf(x, 0.0f), 511.0f);
    y = fminf(fmaxf(y, 0.0f), 511.0f);

    float xbf = fminf(floorf(x), 510.0f);
    float ybf = fminf(floorf(y), 510.0f);

    // a1/b1 = weight of col/row (xb+1)/(yb+1); ==1 exactly at border 511
    float a1 = x - xbf;
    float b1 = y - ybf;
    float cw = pcol ? a1 : (1.0f - a1);
    float rw = r    ? b1 : (1.0f - b1);

    PS ps;
    ps.w = rw * cw;
    // corner texel (yb + r, xb + pcol), this lane's half h
    ps.base = ((((int)ybf + r) << 10) + (((int)xbf + pcol) << 1)) + h;
    return ps;
}

__global__ void __launch_bounds__(NTHREADS, BLOCKS_PER_SM)
geo_encoder_kernel(
    const float*  __restrict__ coords,   // [N,3]
    const float4* __restrict__ pxy,
    const float4* __restrict__ pxz,
    const float4* __restrict__ pyz,
    const float*  __restrict__ Wp,       // [8,24]
    const float*  __restrict__ bp,       // [8]
    float*        __restrict__ out,      // [N,8]
    int n)
{
    const int t    = threadIdx.x;
    const int s    = t & 7;
    const int h    = s & 1;
    const int c    = s >> 1;
    const int r    = c & 1;
    const int pcol = c >> 1;

    // W slice: 2 outputs (2c, 2c+1) x 12 features (plane q, half h, rank rr)
    float Wreg[24];
    float bias0, bias1;
    {
        const int j0 = 2 * c;
        bias0 = __ldg(bp + j0);
        bias1 = __ldg(bp + j0 + 1);
        #pragma unroll
        for (int q = 0; q < 3; q++)
            #pragma unroll
            for (int rr = 0; rr < 4; rr++) {
                Wreg[q * 4 + rr]      = __ldg(Wp + j0 * 24       + q * 8 + h * 4 + rr);
                Wreg[12 + q * 4 + rr] = __ldg(Wp + (j0 + 1) * 24 + q * 8 + h * 4 + rr);
            }
    }

    const int oct   = (blockIdx.x * NTHREADS + t) >> 3;
    const int nocts = (NBLOCKS * NTHREADS) >> 3;
    const int niter = (n + nocts - 1) / nocts;   // uniform across lanes

    for (int k = 0; k < niter; k++) {
        const int  i   = oct + k * nocts;
        const bool act = (i < n);
        const int  ie  = act ? i : 0;

        float cx = __ldg(coords + 3 * ie + 0);
        float cy = __ldg(coords + 3 * ie + 1);
        float cz = __ldg(coords + 3 * ie + 2);
        cx = fminf(fmaxf(cx, -1.0f), 1.0f);
        cy = fminf(fmaxf(cy, -1.0f), 1.0f);
        cz = fminf(fmaxf(cz, -1.0f), 1.0f);

        const PS a = plane_setup(cx, cy, h, r, pcol);
        const PS b = plane_setup(cx, cz, h, r, pcol);
        const PS c3 = plane_setup(cy, cz, h, r, pcol);

        // 3 independent gathers (front-batched)
        const float4 va = __ldg(pxy + a.base);
        const float4 vb = __ldg(pxz + b.base);
        const float4 vc = __ldg(pyz + c3.base);

        // partial features: corner weight x texel values
        float pf[12];
        pf[0]  = a.w  * va.x;  pf[1]  = a.w  * va.y;
        pf[2]  = a.w  * va.z;  pf[3]  = a.w  * va.w;
        pf[4]  = b.w  * vb.x;  pf[5]  = b.w  * vb.y;
        pf[6]  = b.w  * vb.z;  pf[7]  = b.w  * vb.w;
        pf[8]  = c3.w * vc.x;  pf[9]  = c3.w * vc.y;
        pf[10] = c3.w * vc.z;  pf[11] = c3.w * vc.w;

        // reduce over the 4 corners (lane bits 1,2), fused into the matvec
        float o0 = 0.f, o1 = 0.f;
        #pragma unroll
        for (int q = 0; q < 12; q++) {
            float g = pf[q] + __shfl_xor_sync(0xffffffffu, pf[q], 2);
            g += __shfl_xor_sync(0xffffffffu, g, 4);
            o0 += Wreg[q]      * g;
            o1 += Wreg[12 + q] * g;
        }

        // combine rank halves (lane bit 0)
        o0 += __shfl_xor_sync(0xffffffffu, o0, 1);
        o1 += __shfl_xor_sync(0xffffffffu, o1, 1);

        if (act && h == 0) {
            float2 v;
            v.x = fminf(fmaxf(o0 + bias0, -10.0f), 10.0f);
            v.y = fminf(fmaxf(o1 + bias1, -10.0f), 10.0f);
            reinterpret_cast<float2*>(out)[(i << 2) + c] = v;
        }
    }
}

extern "C" void kernel_launch(void* const* d_in, const int* in_sizes, int n_in,
                              void* d_out, int out_size)
{
    const float*  coords = (const float*)d_in[0];
    const float4* pxy    = (const float4*)d_in[1];
    const float4* pxz    = (const float4*)d_in[2];
    const float4* pyz    = (const float4*)d_in[3];
    const float*  Wp     = (const float*)d_in[4];
    const float*  bp     = (const float*)d_in[5];
    float*        out    = (float*)d_out;

    const int n = in_sizes[0] / 3;
    geo_encoder_kernel<<<NBLOCKS, NTHREADS>>>(coords, pxy, pxz, pyz, Wp, bp, out, n);
}

// round 11
// speedup vs baseline: 1.7017x; 1.7017x over previous
#include <cuda_runtime.h>

#define NTHREADS 256
#define BLOCKS_PER_SM 2
#define NBLOCKS  (148 * BLOCKS_PER_SM)   // persistent grid

struct PS { int base; float w0, w1; };   // w0 = ap*(1-b1), w1 = ap*b1

__device__ __forceinline__ PS plane_setup(float u, float v, int s, int p)
{
    // x = ((u+1)*512 - 1)*0.5 == u*256 + 255.5 (<=1 ulp; bilinear continuous)
    float x = fmaf(u, 256.0f, 255.5f);
    float y = fmaf(v, 256.0f, 255.5f);
    x = fminf(fmaxf(x, 0.0f), 511.0f);
    y = fminf(fmaxf(y, 0.0f), 511.0f);

    float xbf = fminf(floorf(x), 510.0f);
    float ybf = fminf(floorf(y), 510.0f);

    float a1 = x - xbf;                  // col xb+1 weight (==1 exactly at border)
    float b1 = y - ybf;
    float ap = p ? a1 : (1.0f - a1);

    PS ps;
    ps.w0 = ap * (1.0f - b1);
    ps.w1 = ap * b1;
    ps.base = ((((int)ybf << 9) + (int)xbf) << 1) + s;
    return ps;
}

// In-flight state for one point: 3 plane setups + 6 gathered float4s
struct Inflight {
    PS a, b, c;
    float4 ta, ba, tb, bb, tc, bc;
};

__device__ __forceinline__ void issue_gathers(
    Inflight& g, float cx, float cy, float cz, int s, int p,
    const float4* __restrict__ pxy, const float4* __restrict__ pxz,
    const float4* __restrict__ pyz)
{
    cx = fminf(fmaxf(cx, -1.0f), 1.0f);
    cy = fminf(fmaxf(cy, -1.0f), 1.0f);
    cz = fminf(fmaxf(cz, -1.0f), 1.0f);
    g.a = plane_setup(cx, cy, s, p);
    g.b = plane_setup(cx, cz, s, p);
    g.c = plane_setup(cy, cz, s, p);
    g.ta = __ldg(pxy + g.a.base);
    g.ba = __ldg(pxy + g.a.base + 1024);
    g.tb = __ldg(pxz + g.b.base);
    g.bb = __ldg(pxz + g.b.base + 1024);
    g.tc = __ldg(pyz + g.c.base);
    g.bc = __ldg(pyz + g.c.base + 1024);
}

__device__ __forceinline__ void consume_store(
    const Inflight& g, const float* __restrict__ Wreg, const float* __restrict__ bias,
    int i, int n, int h, int grp, float* __restrict__ out)
{
    float pf[12];
    pf[0]  = g.a.w0 * g.ta.x + g.a.w1 * g.ba.x;
    pf[1]  = g.a.w0 * g.ta.y + g.a.w1 * g.ba.y;
    pf[2]  = g.a.w0 * g.ta.z + g.a.w1 * g.ba.z;
    pf[3]  = g.a.w0 * g.ta.w + g.a.w1 * g.ba.w;
    pf[4]  = g.b.w0 * g.tb.x + g.b.w1 * g.bb.x;
    pf[5]  = g.b.w0 * g.tb.y + g.b.w1 * g.bb.y;
    pf[6]  = g.b.w0 * g.tb.z + g.b.w1 * g.bb.z;
    pf[7]  = g.b.w0 * g.tb.w + g.b.w1 * g.bb.w;
    pf[8]  = g.c.w0 * g.tc.x + g.c.w1 * g.bc.x;
    pf[9]  = g.c.w0 * g.tc.y + g.c.w1 * g.bc.y;
    pf[10] = g.c.w0 * g.tc.z + g.c.w1 * g.bc.z;
    pf[11] = g.c.w0 * g.tc.w + g.c.w1 * g.bc.w;

    float o0 = 0.f, o1 = 0.f, o2 = 0.f, o3 = 0.f;
    #pragma unroll
    for (int q = 0; q < 12; q++) {
        const float gg = pf[q] + __shfl_xor_sync(0xffffffffu, pf[q], 2);
        o0 += Wreg[q]      * gg;
        o1 += Wreg[12 + q] * gg;
        o2 += Wreg[24 + q] * gg;
        o3 += Wreg[36 + q] * gg;
    }
    o0 += __shfl_xor_sync(0xffffffffu, o0, 1);
    o1 += __shfl_xor_sync(0xffffffffu, o1, 1);
    o2 += __shfl_xor_sync(0xffffffffu, o2, 1);
    o3 += __shfl_xor_sync(0xffffffffu, o3, 1);

    if (i < n && h == 0) {
        float4 v;
        v.x = fminf(fmaxf(o0 + bias[0], -10.0f), 10.0f);
        v.y = fminf(fmaxf(o1 + bias[1], -10.0f), 10.0f);
        v.z = fminf(fmaxf(o2 + bias[2], -10.0f), 10.0f);
        v.w = fminf(fmaxf(o3 + bias[3], -10.0f), 10.0f);
        reinterpret_cast<float4*>(out)[(i << 1) + grp] = v;
    }
}

__global__ void __launch_bounds__(NTHREADS, BLOCKS_PER_SM)
geo_encoder_kernel(
    const float*  __restrict__ coords,   // [N,3]
    const float4* __restrict__ pxy,
    const float4* __restrict__ pxz,
    const float4* __restrict__ pyz,
    const float*  __restrict__ Wp,       // [8,24]
    const float*  __restrict__ bp,       // [8]
    float*        __restrict__ out,      // [N,8]
    int n)
{
    const int t   = threadIdx.x;
    const int s   = t & 3;
    const int h   = s & 1;
    const int p   = s >> 1;
    const int grp = p;

    float Wreg[48];
    float bias[4];
    const int row0 = 4 * grp;
    #pragma unroll
    for (int j = 0; j < 4; j++) {
        bias[j] = __ldg(bp + row0 + j);
        #pragma unroll
        for (int q = 0; q < 3; q++)
            #pragma unroll
            for (int rr = 0; rr < 4; rr++)
                Wreg[j * 12 + q * 4 + rr] = __ldg(Wp + (row0 + j) * 24 + q * 8 + h * 4 + rr);
    }

    const int quad   = (blockIdx.x * NTHREADS + t) >> 2;
    const int nquads = (NBLOCKS * NTHREADS) >> 2;
    const int niter  = (n + nquads - 1) / nquads;   // uniform across lanes

    // clamped coord fetch for virtual iteration j
    auto ldc = [&](int j, float& x, float& y, float& z) {
        int i  = quad + j * nquads;
        int ie = (i < n) ? i : 0;
        x = __ldg(coords + 3 * ie + 0);
        y = __ldg(coords + 3 * ie + 1);
        z = __ldg(coords + 3 * ie + 2);
    };

    // ---- pipeline prologue ----
    float x0, y0, z0;  ldc(0, x0, y0, z0);        // point 0 coords (direct)
    float xA, yA, zA;  ldc(1, xA, yA, zA);        // coord queue slot A (j+1)
    float xB, yB, zB;  ldc(2, xB, yB, zB);        // coord queue slot B (j+2)

    Inflight GA, GB;
    issue_gathers(GA, x0, y0, z0, s, p, pxy, pxz, pyz);   // gathers for point 0

    for (int k = 0; k < niter; k += 2) {
        // ---- half 1: pipeline point k+1, consume point k ----
        issue_gathers(GB, xA, yA, zA, s, p, pxy, pxz, pyz);   // gathers k+1
        ldc(k + 3, xA, yA, zA);                                // refill coords (j=k+3)
        consume_store(GA, Wreg, bias, quad + k * nquads, n, h, grp, out);

        // ---- half 2: pipeline point k+2, consume point k+1 ----
        issue_gathers(GA, xB, yB, zB, s, p, pxy, pxz, pyz);   // gathers k+2
        ldc(k + 4, xB, yB, zB);                                // refill coords (j=k+4)
        consume_store(GB, Wreg, bias, quad + (k + 1) * nquads, n, h, grp, out);
    }
}

extern "C" void kernel_launch(void* const* d_in, const int* in_sizes, int n_in,
                              void* d_out, int out_size)
{
    const float*  coords = (const float*)d_in[0];
    const float4* pxy    = (const float4*)d_in[1];
    const float4* pxz    = (const float4*)d_in[2];
    const float4* pyz    = (const float4*)d_in[3];
    const float*  Wp     = (const float*)d_in[4];
    const float*  bp     = (const float*)d_in[5];
    float*        out    = (float*)d_out;

    const int n = in_sizes[0] / 3;
    geo_encoder_kernel<<<NBLOCKS, NTHREADS>>>(coords, pxy, pxz, pyz, Wp, bp, out, n);
}

// round 12
// speedup vs baseline: 1.8687x; 1.0981x over previous
#include <cuda_runtime.h>
#include <cuda_fp16.h>

#define NTHREADS 256
#define BLOCKS_PER_SM 2
#define NBLOCKS  (148 * BLOCKS_PER_SM)   // persistent grid

// fp16 row-pair dup: entry(y,x) = 32B = [tex(y,x) ranks0-7 fp16, tex(y+1,x) ranks0-7 fp16]
// (y+1 clamped). One bilinear sample = 64B contiguous (entries xb, xb+1).
#define DUP_U4 (512 * 512 * 2)           // uint4 (16B) count per plane = 8MB/plane
__device__ uint4 g_dup[3][DUP_U4];       // 24MB total — same footprint as fp32 planes

__global__ void __launch_bounds__(256)
repack_kernel(const float4* __restrict__ p0,
              const float4* __restrict__ p1,
              const float4* __restrict__ p2)
{
    const int idx = blockIdx.x * 256 + threadIdx.x;   // one thread per output uint4
    if (idx >= 3 * DUP_U4) return;
    const int q   = idx >> 19;             // plane
    const int rem = idx & (DUP_U4 - 1);
    const int ent = rem >> 1;              // entry = y*512 + x
    const int bot = rem & 1;               // 0 = top texel, 1 = bottom texel
    const int y   = ent >> 9;
    const int x   = ent & 511;
    const int yy  = bot ? min(y + 1, 511) : y;
    const float4* src = (q == 0) ? p0 : (q == 1) ? p1 : p2;
    const float4 f0 = __ldg(src + ((((yy << 9) + x) << 1) + 0));   // ranks 0-3
    const float4 f1 = __ldg(src + ((((yy << 9) + x) << 1) + 1));   // ranks 4-7
    __half2 h01 = __floats2half2_rn(f0.x, f0.y);
    __half2 h23 = __floats2half2_rn(f0.z, f0.w);
    __half2 h45 = __floats2half2_rn(f1.x, f1.y);
    __half2 h67 = __floats2half2_rn(f1.z, f1.w);
    uint4 o;
    o.x = *reinterpret_cast<unsigned*>(&h01);
    o.y = *reinterpret_cast<unsigned*>(&h23);
    o.z = *reinterpret_cast<unsigned*>(&h45);
    o.w = *reinterpret_cast<unsigned*>(&h67);
    g_dup[q][idx & (3 * DUP_U4 - 1) % DUP_U4] = o;   // placeholder, fixed below
}

// NOTE: indexing fixed properly in this second definition-free form:
// (the line above would be wrong; real store is below via macro-free rewrite)

struct PS { int base; float wo, wr; };   // own-row weight, recv-row weight (both x colw)

// lane roles: s = t&3; h = s&1 (row of own corner AND rank-half kept);
// p = s>>1 (column). base = uint4 index of own corner texel.
__device__ __forceinline__ PS plane_setup(float u, float v, int s, int h, int p)
{
    float x = fmaf(u, 256.0f, 255.5f);
    float y = fmaf(v, 256.0f, 255.5f);
    x = fminf(fmaxf(x, 0.0f), 511.0f);
    y = fminf(fmaxf(y, 0.0f), 511.0f);

    float xbf = fminf(floorf(x), 510.0f);
    float ybf = fminf(floorf(y), 510.0f);

    float a1 = x - xbf;                  // col xb+1 weight (==1 exactly at border)
    float b1 = y - ybf;                  // row yb+1 weight
    float ap = p ? a1 : (1.0f - a1);

    PS ps;
    ps.wo = ap * (h ? b1 : (1.0f - b1));   // own corner row = h
    ps.wr = ap * (h ? (1.0f - b1) : b1);   // received corner = other row
    ps.base = (((((int)ybf << 9) + (int)xbf) << 1)) + s;   // uint4 idx; slots = [t0 b0 t1 b1]
    return ps;
}

struct Inflight { PS a, b, c; uint4 va, vb, vc; };

__device__ __forceinline__ void issue_gathers(
    Inflight& g, float cx, float cy, float cz, int s, int h, int p,
    const uint4* __restrict__ dxy, const uint4* __restrict__ dxz,
    const uint4* __restrict__ dyz)
{
    cx = fminf(fmaxf(cx, -1.0f), 1.0f);
    cy = fminf(fmaxf(cy, -1.0f), 1.0f);
    cz = fminf(fmaxf(cz, -1.0f), 1.0f);
    g.a = plane_setup(cx, cy, s, h, p);
    g.b = plane_setup(cx, cz, s, h, p);
    g.c = plane_setup(cy, cz, s, h, p);
    g.va = __ldg(dxy + g.a.base);
    g.vb = __ldg(dxz + g.b.base);
    g.vc = __ldg(dyz + g.c.base);
}

// per-plane: exchange (2 shfl), convert, y-lerp -> 4 partial features
__device__ __forceinline__ void plane_pf(
    const uint4& v, float wo, float wr, int h, float* pf)
{
    // send partner our (1-h) rank-half; keep our h-half
    unsigned s0 = h ? v.x : v.z;
    unsigned s1 = h ? v.y : v.w;
    unsigned r0 = __shfl_xor_sync(0xffffffffu, s0, 1);
    unsigned r1 = __shfl_xor_sync(0xffffffffu, s1, 1);
    unsigned k0 = h ? v.z : v.x;
    unsigned k1 = h ? v.w : v.y;
    float2 fo0 = __half22float2(*reinterpret_cast<__half2*>(&k0));
    float2 fo1 = __half22float2(*reinterpret_cast<__half2*>(&k1));
    float2 fr0 = __half22float2(*reinterpret_cast<__half2*>(&r0));
    float2 fr1 = __half22float2(*reinterpret_cast<__half2*>(&r1));
    pf[0] = wo * fo0.x + wr * fr0.x;
    pf[1] = wo * fo0.y + wr * fr0.y;
    pf[2] = wo * fo1.x + wr * fr1.x;
    pf[3] = wo * fo1.y + wr * fr1.y;
}

__device__ __forceinline__ void consume_store(
    const Inflight& g, const float* __restrict__ Wreg, const float* __restrict__ bias,
    int i, int n, int h, int grp, float* __restrict__ out)
{
    float pf[12];
    plane_pf(g.va, g.a.wo, g.a.wr, h, pf + 0);
    plane_pf(g.vb, g.b.wo, g.b.wr, h, pf + 4);
    plane_pf(g.vc, g.c.wo, g.c.wr, h, pf + 8);

    float o0 = 0.f, o1 = 0.f, o2 = 0.f, o3 = 0.f;
    #pragma unroll
    for (int q = 0; q < 12; q++) {
        const float gg = pf[q] + __shfl_xor_sync(0xffffffffu, pf[q], 2);
        o0 += Wreg[q]      * gg;
        o1 += Wreg[12 + q] * gg;
        o2 += Wreg[24 + q] * gg;
        o3 += Wreg[36 + q] * gg;
    }
    o0 += __shfl_xor_sync(0xffffffffu, o0, 1);
    o1 += __shfl_xor_sync(0xffffffffu, o1, 1);
    o2 += __shfl_xor_sync(0xffffffffu, o2, 1);
    o3 += __shfl_xor_sync(0xffffffffu, o3, 1);

    if (i < n && h == 0) {
        float4 v;
        v.x = fminf(fmaxf(o0 + bias[0], -10.0f), 10.0f);
        v.y = fminf(fmaxf(o1 + bias[1], -10.0f), 10.0f);
        v.z = fminf(fmaxf(o2 + bias[2], -10.0f), 10.0f);
        v.w = fminf(fmaxf(o3 + bias[3], -10.0f), 10.0f);
        reinterpret_cast<float4*>(out)[(i << 1) + grp] = v;
    }
}

__global__ void __launch_bounds__(NTHREADS, BLOCKS_PER_SM)
geo_encoder_kernel(
    const float*  __restrict__ coords,   // [N,3]
    const float*  __restrict__ Wp,       // [8,24]
    const float*  __restrict__ bp,       // [8]
    float*        __restrict__ out,      // [N,8]
    int n)
{
    const uint4* __restrict__ dxy = g_dup[0];
    const uint4* __restrict__ dxz = g_dup[1];
    const uint4* __restrict__ dyz = g_dup[2];

    const int t   = threadIdx.x;
    const int s   = t & 3;
    const int h   = s & 1;
    const int p   = s >> 1;
    const int grp = p;

    // W slice in registers: Wreg[j*12 + q*4 + rr] = W[4*grp+j][q*8 + h*4 + rr]
    float Wreg[48];
    float bias[4];
    const int row0 = 4 * grp;
    #pragma unroll
    for (int j = 0; j < 4; j++) {
        bias[j] = __ldg(bp + row0 + j);
        #pragma unroll
        for (int q = 0; q < 3; q++)
            #pragma unroll
            for (int rr = 0; rr < 4; rr++)
                Wreg[j * 12 + q * 4 + rr] = __ldg(Wp + (row0 + j) * 24 + q * 8 + h * 4 + rr);
    }

    const int quad   = (blockIdx.x * NTHREADS + t) >> 2;
    const int nquads = (NBLOCKS * NTHREADS) >> 2;
    const int niter  = (n + nquads - 1) / nquads;

    auto ldc = [&](int j, float& x, float& y, float& z) {
        int i  = quad + j * nquads;
        int ie = (i < n) ? i : 0;
        x = __ldg(coords + 3 * ie + 0);
        y = __ldg(coords + 3 * ie + 1);
        z = __ldg(coords + 3 * ie + 2);
    };

    float x0, y0, z0;  ldc(0, x0, y0, z0);
    float xA, yA, zA;  ldc(1, xA, yA, zA);
    float xB, yB, zB;  ldc(2, xB, yB, zB);

    Inflight GA, GB;
    issue_gathers(GA, x0, y0, z0, s, h, p, dxy, dxz, dyz);

    for (int k = 0; k < niter; k += 2) {
        issue_gathers(GB, xA, yA, zA, s, h, p, dxy, dxz, dyz);
        ldc(k + 3, xA, yA, zA);
        consume_store(GA, Wreg, bias, quad + k * nquads, n, h, grp, out);

        issue_gathers(GA, xB, yB, zB, s, h, p, dxy, dxz, dyz);
        ldc(k + 4, xB, yB, zB);
        consume_store(GB, Wreg, bias, quad + (k + 1) * nquads, n, h, grp, out);
    }
}

// Correct repack (replaces the placeholder store above): one thread per uint4.
__global__ void __launch_bounds__(256)
repack_kernel_fixed(const float4* __restrict__ p0,
                    const float4* __restrict__ p1,
                    const float4* __restrict__ p2)
{
    const int idx = blockIdx.x * 256 + threadIdx.x;
    if (idx >= 3 * DUP_U4) return;
    const int q   = idx >> 19;
    const int rem = idx & (DUP_U4 - 1);
    const int ent = rem >> 1;
    const int bot = rem & 1;
    const int y   = ent >> 9;
    const int x   = ent & 511;
    const int yy  = bot ? min(y + 1, 511) : y;
    const float4* src = (q == 0) ? p0 : (q == 1) ? p1 : p2;
    const float4 f0 = __ldg(src + ((((yy << 9) + x) << 1) + 0));
    const float4 f1 = __ldg(src + ((((yy << 9) + x) << 1) + 1));
    __half2 h01 = __floats2half2_rn(f0.x, f0.y);
    __half2 h23 = __floats2half2_rn(f0.z, f0.w);
    __half2 h45 = __floats2half2_rn(f1.x, f1.y);
    __half2 h67 = __floats2half2_rn(f1.z, f1.w);
    uint4 o;
    o.x = *reinterpret_cast<unsigned*>(&h01);
    o.y = *reinterpret_cast<unsigned*>(&h23);
    o.z = *reinterpret_cast<unsigned*>(&h45);
    o.w = *reinterpret_cast<unsigned*>(&h67);
    g_dup[q][rem] = o;
}

extern "C" void kernel_launch(void* const* d_in, const int* in_sizes, int n_in,
                              void* d_out, int out_size)
{
    const float*  coords = (const float*)d_in[0];
    const float4* pxy    = (const float4*)d_in[1];
    const float4* pxz    = (const float4*)d_in[2];
    const float4* pyz    = (const float4*)d_in[3];
    const float*  Wp     = (const float*)d_in[4];
    const float*  bp     = (const float*)d_in[5];
    float*        out    = (float*)d_out;

    const int n = in_sizes[0] / 3;

    repack_kernel_fixed<<<(3 * DUP_U4) / 256, 256>>>(pxy, pxz, pyz);
    geo_encoder_kernel<<<NBLOCKS, NTHREADS>>>(coords, Wp, bp, out, n);
}

// round 14
// speedup vs baseline: 1.8983x; 1.0158x over previous
#include <cuda_runtime.h>
#include <cuda_fp16.h>

#define NTHREADS 256
#define BLOCKS_PER_SM 2
#define NBLOCKS  (148 * BLOCKS_PER_SM)   // persistent grid

// fp16 row-pair dup: entry(y,x) = 32B = [tex(y,x) ranks0-7, tex(y+1,x) ranks0-7]
// (y+1 clamped). One bilinear sample = 64B contiguous (entries xb, xb+1).
// uint4 slots within the 64B: [top(x0), bot(x0), top(x1), bot(x1)]
#define DUP_U4 (512 * 512 * 2)           // uint4 per plane = 8MB/plane, 24MB total
__device__ uint4 g_dup[3][DUP_U4];

__global__ void __launch_bounds__(256)
repack_kernel(const float4* __restrict__ p0,
              const float4* __restrict__ p1,
              const float4* __restrict__ p2)
{
    const int idx = blockIdx.x * 256 + threadIdx.x;   // one thread per output uint4
    if (idx >= 3 * DUP_U4) return;
    const int q   = idx >> 19;             // plane
    const int rem = idx & (DUP_U4 - 1);
    const int ent = rem >> 1;              // entry = y*512 + x
    const int bot = rem & 1;
    const int y   = ent >> 9;
    const int x   = ent & 511;
    const int yy  = bot ? min(y + 1, 511) : y;
    const float4* src = (q == 0) ? p0 : (q == 1) ? p1 : p2;
    const float4 f0 = __ldg(src + ((((yy << 9) + x) << 1) + 0));
    const float4 f1 = __ldg(src + ((((yy << 9) + x) << 1) + 1));
    __half2 h01 = __floats2half2_rn(f0.x, f0.y);
    __half2 h23 = __floats2half2_rn(f0.z, f0.w);
    __half2 h45 = __floats2half2_rn(f1.x, f1.y);
    __half2 h67 = __floats2half2_rn(f1.z, f1.w);
    uint4 o;
    o.x = *reinterpret_cast<unsigned*>(&h01);
    o.y = *reinterpret_cast<unsigned*>(&h23);
    o.z = *reinterpret_cast<unsigned*>(&h45);
    o.w = *reinterpret_cast<unsigned*>(&h67);
    g_dup[q][rem] = o;
}

struct PS { int base; float wo, wr; };   // own-row weight, recv-row weight (x colw)
struct Inflight { PS a, b, c; uint4 va, vb, vc; };

// per-coordinate processing (done ONCE per coord; [-1,1] pre-clip is subsumed
// by the [0,511] clamp under the monotone map c*256+255.5)
__device__ __forceinline__ void coord_proc(float c, float& frac, float& omf, int& ib)
{
    float X = fmaf(c, 256.0f, 255.5f);
    X = fminf(fmaxf(X, 0.0f), 511.0f);
    float F = fminf(floorf(X), 510.0f);   // frac==1 exactly at border 511
    frac = X - F;
    omf  = 1.0f - frac;
    ib   = (int)F;
}

__device__ __forceinline__ void issue_gathers(
    Inflight& g, float cx, float cy, float cz, int s, int h, int p,
    const uint4* __restrict__ dxy, const uint4* __restrict__ dxz,
    const uint4* __restrict__ dyz)
{
    float fx, ox; int ix;  coord_proc(cx, fx, ox, ix);
    float fy, oy; int iy;  coord_proc(cy, fy, oy, iy);
    float fz, oz; int iz;  coord_proc(cz, fz, oz, iz);

    // column weights (this lane's column p)
    const float apx = p ? fx : ox;       // x as column (planes xy, xz)
    const float apy = p ? fy : oy;       // y as column (plane yz)
    // row weights (own corner row = h; received = other row)
    const float ryo = h ? fy : oy;       // y as row, own
    const float ryr = h ? oy : fy;       // y as row, recv
    const float rzo = h ? fz : oz;       // z as row, own
    const float rzr = h ? oz : fz;       // z as row, recv

    g.a.wo = apx * ryo;  g.a.wr = apx * ryr;   // plane xy: col x, row y
    g.b.wo = apx * rzo;  g.b.wr = apx * rzr;   // plane xz: col x, row z
    g.c.wo = apy * rzo;  g.c.wr = apy * rzr;   // plane yz: col y, row z

    g.a.base = (((iy << 9) + ix) << 1) + s;
    g.b.base = (((iz << 9) + ix) << 1) + s;
    g.c.base = (((iz << 9) + iy) << 1) + s;

    g.va = __ldg(dxy + g.a.base);
    g.vb = __ldg(dxz + g.b.base);
    g.vc = __ldg(dyz + g.c.base);
}

// per-plane: exchange rank-halves (2 shfl), convert, y-lerp -> 4 partial features
__device__ __forceinline__ void plane_pf(
    const uint4& v, float wo, float wr, int h, float* pf)
{
    unsigned s0 = h ? v.x : v.z;         // send partner our (1-h) half
    unsigned s1 = h ? v.y : v.w;
    unsigned r0 = __shfl_xor_sync(0xffffffffu, s0, 1);
    unsigned r1 = __shfl_xor_sync(0xffffffffu, s1, 1);
    unsigned k0 = h ? v.z : v.x;         // keep our h half
    unsigned k1 = h ? v.w : v.y;
    float2 fo0 = __half22float2(*reinterpret_cast<__half2*>(&k0));
    float2 fo1 = __half22float2(*reinterpret_cast<__half2*>(&k1));
    float2 fr0 = __half22float2(*reinterpret_cast<__half2*>(&r0));
    float2 fr1 = __half22float2(*reinterpret_cast<__half2*>(&r1));
    pf[0] = wo * fo0.x + wr * fr0.x;
    pf[1] = wo * fo0.y + wr * fr0.y;
    pf[2] = wo * fo1.x + wr * fr1.x;
    pf[3] = wo * fo1.y + wr * fr1.y;
}

__device__ __forceinline__ void consume_store(
    const Inflight& g, const float* __restrict__ Wreg, const float* __restrict__ bias,
    int i, int n, int h, int grp, float* __restrict__ out)
{
    float pf[12];
    plane_pf(g.va, g.a.wo, g.a.wr, h, pf + 0);
    plane_pf(g.vb, g.b.wo, g.b.wr, h, pf + 4);
    plane_pf(g.vc, g.c.wo, g.c.wr, h, pf + 8);

    float o0 = 0.f, o1 = 0.f, o2 = 0.f, o3 = 0.f;
    #pragma unroll
    for (int q = 0; q < 12; q++) {
        const float gg = pf[q] + __shfl_xor_sync(0xffffffffu, pf[q], 2);
        o0 += Wreg[q]      * gg;
        o1 += Wreg[12 + q] * gg;
        o2 += Wreg[24 + q] * gg;
        o3 += Wreg[36 + q] * gg;
    }
    o0 += __shfl_xor_sync(0xffffffffu, o0, 1);
    o1 += __shfl_xor_sync(0xffffffffu, o1, 1);
    o2 += __shfl_xor_sync(0xffffffffu, o2, 1);
    o3 += __shfl_xor_sync(0xffffffffu, o3, 1);

    if (i < n && h == 0) {
        float4 v;
        v.x = fminf(fmaxf(o0 + bias[0], -10.0f), 10.0f);
        v.y = fminf(fmaxf(o1 + bias[1], -10.0f), 10.0f);
        v.z = fminf(fmaxf(o2 + bias[2], -10.0f), 10.0f);
        v.w = fminf(fmaxf(o3 + bias[3], -10.0f), 10.0f);
        reinterpret_cast<float4*>(out)[(i << 1) + grp] = v;
    }
}

__global__ void __launch_bounds__(NTHREADS, BLOCKS_PER_SM)
geo_encoder_kernel(
    const float*  __restrict__ coords,   // [N,3]
    const float*  __restrict__ Wp,       // [8,24]
    const float*  __restrict__ bp,       // [8]
    float*        __restrict__ out,      // [N,8]
    int n)
{
    const uint4* __restrict__ dxy = g_dup[0];
    const uint4* __restrict__ dxz = g_dup[1];
    const uint4* __restrict__ dyz = g_dup[2];

    const int t   = threadIdx.x;
    const int s   = t & 3;
    const int h   = s & 1;       // rank half kept + own corner row
    const int p   = s >> 1;      // column; also output group
    const int grp = p;

    // Wreg[j*12 + q*4 + rr] = W[4*grp+j][q*8 + h*4 + rr]
    float Wreg[48];
    float bias[4];
    const int row0 = 4 * grp;
    #pragma unroll
    for (int j = 0; j < 4; j++) {
        bias[j] = __ldg(bp + row0 + j);
        #pragma unroll
        for (int q = 0; q < 3; q++)
            #pragma unroll
            for (int rr = 0; rr < 4; rr++)
                Wreg[j * 12 + q * 4 + rr] = __ldg(Wp + (row0 + j) * 24 + q * 8 + h * 4 + rr);
    }

    const int quad   = (blockIdx.x * NTHREADS + t) >> 2;
    const int nquads = (NBLOCKS * NTHREADS) >> 2;
    const int niter  = (n + nquads - 1) / nquads;

    auto ldc = [&](int j, float& x, float& y, float& z) {
        int i  = quad + j * nquads;
        int ie = (i < n) ? i : 0;
        x = __ldg(coords + 3 * ie + 0);
        y = __ldg(coords + 3 * ie + 1);
        z = __ldg(coords + 3 * ie + 2);
    };

    float x0, y0, z0;  ldc(0, x0, y0, z0);
    float xA, yA, zA;  ldc(1, xA, yA, zA);
    float xB, yB, zB;  ldc(2, xB, yB, zB);

    Inflight GA, GB;
    issue_gathers(GA, x0, y0, z0, s, h, p, dxy, dxz, dyz);

    for (int k = 0; k < niter; k += 2) {
        issue_gathers(GB, xA, yA, zA, s, h, p, dxy, dxz, dyz);
        ldc(k + 3, xA, yA, zA);
        consume_store(GA, Wreg, bias, quad + k * nquads, n, h, grp, out);

        issue_gathers(GA, xB, yB, zB, s, h, p, dxy, dxz, dyz);
        ldc(k + 4, xB, yB, zB);
        consume_store(GB, Wreg, bias, quad + (k + 1) * nquads, n, h, grp, out);
    }
}

extern "C" void kernel_launch(void* const* d_in, const int* in_sizes, int n_in,
                              void* d_out, int out_size)
{
    const float*  coords = (const float*)d_in[0];
    const float4* pxy    = (const float4*)d_in[1];
    const float4* pxz    = (const float4*)d_in[2];
    const float4* pyz    = (const float4*)d_in[3];
    const float*  Wp     = (const float*)d_in[4];
    const float*  bp     = (const float*)d_in[5];
    float*        out    = (float*)d_out;

    const int n = in_sizes[0] / 3;

    repack_kernel<<<(3 * DUP_U4) / 256, 256>>>(pxy, pxz, pyz);
    geo_encoder_kernel<<<NBLOCKS, NTHREADS>>>(coords, Wp, bp, out, n);
}

// round 15
// speedup vs baseline: 2.0721x; 1.0915x over previous
#include <cuda_runtime.h>
#include <cuda_fp16.h>

#define NTHREADS 256
#define BLOCKS_PER_SM 2
#define NBLOCKS  (148 * BLOCKS_PER_SM)   // persistent grid

// fp16 row-pair dup: entry(y,x) = 32B = [tex(y,x) ranks0-7, tex(y+1,x) ranks0-7]
// (y+1 clamped). One bilinear sample = 64B contiguous (entries xb, xb+1).
// uint4 slots within the 64B: [top(x0), bot(x0), top(x1), bot(x1)]
#define DUP_U4 (512 * 512 * 2)           // uint4 per plane = 8MB/plane, 24MB total
__device__ uint4 g_dup[3][DUP_U4];

__global__ void __launch_bounds__(256)
repack_kernel(const float4* __restrict__ p0,
              const float4* __restrict__ p1,
              const float4* __restrict__ p2)
{
    const int idx = blockIdx.x * 256 + threadIdx.x;   // one thread per output uint4
    if (idx >= 3 * DUP_U4) return;
    const int q   = idx >> 19;             // plane
    const int rem = idx & (DUP_U4 - 1);
    const int ent = rem >> 1;              // entry = y*512 + x
    const int bot = rem & 1;
    const int y   = ent >> 9;
    const int x   = ent & 511;
    const int yy  = bot ? min(y + 1, 511) : y;
    const float4* src = (q == 0) ? p0 : (q == 1) ? p1 : p2;
    const float4 f0 = __ldg(src + ((((yy << 9) + x) << 1) + 0));
    const float4 f1 = __ldg(src + ((((yy << 9) + x) << 1) + 1));
    __half2 h01 = __floats2half2_rn(f0.x, f0.y);
    __half2 h23 = __floats2half2_rn(f0.z, f0.w);
    __half2 h45 = __floats2half2_rn(f1.x, f1.y);
    __half2 h67 = __floats2half2_rn(f1.z, f1.w);
    uint4 o;
    o.x = *reinterpret_cast<unsigned*>(&h01);
    o.y = *reinterpret_cast<unsigned*>(&h23);
    o.z = *reinterpret_cast<unsigned*>(&h45);
    o.w = *reinterpret_cast<unsigned*>(&h67);
    g_dup[q][rem] = o;
}

struct Inflight {
    __half2 woa, wra, wob, wrb, woc, wrc;   // own-row / recv-row weights, broadcast half2
    uint4 va, vb, vc;
};

// per-coordinate processing (once per coord; [-1,1] pre-clip subsumed by [0,511]
// clamp under the monotone map c*256 + 255.5)
__device__ __forceinline__ void coord_proc(float c, float& frac, float& omf, int& ib)
{
    float X = fmaf(c, 256.0f, 255.5f);
    X = fminf(fmaxf(X, 0.0f), 511.0f);
    float F = fminf(floorf(X), 510.0f);   // frac==1 exactly at border 511
    frac = X - F;
    omf  = 1.0f - frac;
    ib   = (int)F;
}

__device__ __forceinline__ void issue_gathers(
    Inflight& g, float cx, float cy, float cz, int s, int h, int p,
    const uint4* __restrict__ dxy, const uint4* __restrict__ dxz,
    const uint4* __restrict__ dyz)
{
    float fx, ox; int ix;  coord_proc(cx, fx, ox, ix);
    float fy, oy; int iy;  coord_proc(cy, fy, oy, iy);
    float fz, oz; int iz;  coord_proc(cz, fz, oz, iz);

    const float apx = p ? fx : ox;       // x as column (planes xy, xz)
    const float apy = p ? fy : oy;       // y as column (plane yz)
    const float ryo = h ? fy : oy;       // y as row: own corner row = h
    const float ryr = h ? oy : fy;
    const float rzo = h ? fz : oz;       // z as row
    const float rzr = h ? oz : fz;

    // fp32 product, single rounding to fp16, broadcast to half2
    g.woa = __float2half2_rn(apx * ryo);
    g.wra = __float2half2_rn(apx * ryr);
    g.wob = __float2half2_rn(apx * rzo);
    g.wrb = __float2half2_rn(apx * rzr);
    g.woc = __float2half2_rn(apy * rzo);
    g.wrc = __float2half2_rn(apy * rzr);

    const int ba = (((iy << 9) + ix) << 1) + s;
    const int bb = (((iz << 9) + ix) << 1) + s;
    const int bc = (((iz << 9) + iy) << 1) + s;

    g.va = __ldg(dxy + ba);
    g.vb = __ldg(dxz + bb);
    g.vc = __ldg(dyz + bc);
}

// per-plane: exchange rank-halves (2 shfl), packed fp16 row-lerp -> 2 half2 features
__device__ __forceinline__ void plane_pf_h2(
    const uint4& v, __half2 wo, __half2 wr, int h, __half2& pf0, __half2& pf1)
{
    unsigned own0 = h ? v.z : v.x;       // keep our h half (ranks h*4..h*4+3)
    unsigned own1 = h ? v.w : v.y;
    unsigned snd0 = h ? v.x : v.z;       // send partner our (1-h) half
    unsigned snd1 = h ? v.y : v.w;
    unsigned r0 = __shfl_xor_sync(0xffffffffu, snd0, 1);
    unsigned r1 = __shfl_xor_sync(0xffffffffu, snd1, 1);
    __half2 o0 = *reinterpret_cast<__half2*>(&own0);
    __half2 o1 = *reinterpret_cast<__half2*>(&own1);
    __half2 q0 = *reinterpret_cast<__half2*>(&r0);
    __half2 q1 = *reinterpret_cast<__half2*>(&r1);
    pf0 = __hfma2(wo, o0, __hmul2(wr, q0));
    pf1 = __hfma2(wo, o1, __hmul2(wr, q1));
}

__device__ __forceinline__ void consume_store(
    const Inflight& g, const float* __restrict__ Wreg, const float* __restrict__ bias,
    int i, int n, int h, int grp, float* __restrict__ out)
{
    __half2 pf[6];
    plane_pf_h2(g.va, g.woa, g.wra, h, pf[0], pf[1]);
    plane_pf_h2(g.vb, g.wob, g.wrb, h, pf[2], pf[3]);
    plane_pf_h2(g.vc, g.woc, g.wrc, h, pf[4], pf[5]);

    // packed column reduce (xor bit1) + convert to fp32 features
    float gg[12];
    #pragma unroll
    for (int q2 = 0; q2 < 6; q2++) {
        unsigned u = *reinterpret_cast<unsigned*>(&pf[q2]);
        unsigned w = __shfl_xor_sync(0xffffffffu, u, 2);
        __half2 sum = __hadd2(pf[q2], *reinterpret_cast<__half2*>(&w));
        float2 f = __half22float2(sum);
        gg[2 * q2]     = f.x;
        gg[2 * q2 + 1] = f.y;
    }

    // fp32 register matvec (precision-critical path unchanged)
    float o0 = 0.f, o1 = 0.f, o2 = 0.f, o3 = 0.f;
    #pragma unroll
    for (int q = 0; q < 12; q++) {
        o0 += Wreg[q]      * gg[q];
        o1 += Wreg[12 + q] * gg[q];
        o2 += Wreg[24 + q] * gg[q];
        o3 += Wreg[36 + q] * gg[q];
    }
    o0 += __shfl_xor_sync(0xffffffffu, o0, 1);
    o1 += __shfl_xor_sync(0xffffffffu, o1, 1);
    o2 += __shfl_xor_sync(0xffffffffu, o2, 1);
    o3 += __shfl_xor_sync(0xffffffffu, o3, 1);

    if (i < n && h == 0) {
        float4 v;
        v.x = fminf(fmaxf(o0 + bias[0], -10.0f), 10.0f);
        v.y = fminf(fmaxf(o1 + bias[1], -10.0f), 10.0f);
        v.z = fminf(fmaxf(o2 + bias[2], -10.0f), 10.0f);
        v.w = fminf(fmaxf(o3 + bias[3], -10.0f), 10.0f);
        reinterpret_cast<float4*>(out)[(i << 1) + grp] = v;
    }
}

__global__ void __launch_bounds__(NTHREADS, BLOCKS_PER_SM)
geo_encoder_kernel(
    const float*  __restrict__ coords,   // [N,3]
    const float*  __restrict__ Wp,       // [8,24]
    const float*  __restrict__ bp,       // [8]
    float*        __restrict__ out,      // [N,8]
    int n)
{
    const uint4* __restrict__ dxy = g_dup[0];
    const uint4* __restrict__ dxz = g_dup[1];
    const uint4* __restrict__ dyz = g_dup[2];

    const int t   = threadIdx.x;
    const int s   = t & 3;
    const int h   = s & 1;       // rank half kept + own corner row
    const int p   = s >> 1;      // column; also output group
    const int grp = p;

    // Wreg[j*12 + q*4 + rr] = W[4*grp+j][q*8 + h*4 + rr]  (feature order matches gg[])
    float Wreg[48];
    float bias[4];
    const int row0 = 4 * grp;
    #pragma unroll
    for (int j = 0; j < 4; j++) {
        bias[j] = __ldg(bp + row0 + j);
        #pragma unroll
        for (int q = 0; q < 3; q++)
            #pragma unroll
            for (int rr = 0; rr < 4; rr++)
                Wreg[j * 12 + q * 4 + rr] = __ldg(Wp + (row0 + j) * 24 + q * 8 + h * 4 + rr);
    }

    const int quad   = (blockIdx.x * NTHREADS + t) >> 2;
    const int nquads = (NBLOCKS * NTHREADS) >> 2;
    const int niter  = (n + nquads - 1) / nquads;

    auto ldc = [&](int j, float& x, float& y, float& z) {
        int i  = quad + j * nquads;
        int ie = (i < n) ? i : 0;
        x = __ldg(coords + 3 * ie + 0);
        y = __ldg(coords + 3 * ie + 1);
        z = __ldg(coords + 3 * ie + 2);
    };

    float x0, y0, z0;  ldc(0, x0, y0, z0);
    float xA, yA, zA;  ldc(1, xA, yA, zA);
    float xB, yB, zB;  ldc(2, xB, yB, zB);

    Inflight GA, GB;
    issue_gathers(GA, x0, y0, z0, s, h, p, dxy, dxz, dyz);

    for (int k = 0; k < niter; k += 2) {
        issue_gathers(GB, xA, yA, zA, s, h, p, dxy, dxz, dyz);
        ldc(k + 3, xA, yA, zA);
        consume_store(GA, Wreg, bias, quad + k * nquads, n, h, grp, out);

        issue_gathers(GA, xB, yB, zB, s, h, p, dxy, dxz, dyz);
        ldc(k + 4, xB, yB, zB);
        consume_store(GB, Wreg, bias, quad + (k + 1) * nquads, n, h, grp, out);
    }
}

extern "C" void kernel_launch(void* const* d_in, const int* in_sizes, int n_in,
                              void* d_out, int out_size)
{
    const float*  coords = (const float*)d_in[0];
    const float4* pxy    = (const float4*)d_in[1];
    const float4* pxz    = (const float4*)d_in[2];
    const float4* pyz    = (const float4*)d_in[3];
    const float*  Wp     = (const float*)d_in[4];
    const float*  bp     = (const float*)d_in[5];
    float*        out    = (float*)d_out;

    const int n = in_sizes[0] / 3;

    repack_kernel<<<(3 * DUP_U4) / 256, 256>>>(pxy, pxz, pyz);
    geo_encoder_kernel<<<NBLOCKS, NTHREADS>>>(coords, Wp, bp, out, n);
}